// round 8
// baseline (speedup 1.0000x reference)
#include <cuda_runtime.h>
#include <cuda_bf16.h>
#include <cstdint>

#define NT 1024   // tokens
#define ND 1024   // model dim
#define NH 512    // hidden dim
#define NE 8      // experts

// ---- static scratch ----
__device__ int   g_cnt[NE];
__device__ int   g_tok[NE * NT];
__device__ float g_scl[NE * NT];
__device__ __nv_bfloat16 g_ah[(size_t)NE * NT * ND];   // routed A, hi
__device__ __nv_bfloat16 g_al[(size_t)NE * NT * ND];   // routed A, lo
__device__ __nv_bfloat16 g_hh[(size_t)NE * NT * NH];   // hidden hi
__device__ __nv_bfloat16 g_hl[(size_t)NE * NT * NH];   // hidden lo
__device__ __nv_bfloat16 g_w1h[(size_t)NE * ND * NH];  // weights pre-split (k-major)
__device__ __nv_bfloat16 g_w1l[(size_t)NE * ND * NH];
__device__ __nv_bfloat16 g_w3h[(size_t)NE * ND * NH];
__device__ __nv_bfloat16 g_w3l[(size_t)NE * ND * NH];
__device__ __nv_bfloat16 g_w2h[(size_t)NE * NH * ND];
__device__ __nv_bfloat16 g_w2l[(size_t)NE * NH * ND];

// ===================== helpers =====================
__device__ __forceinline__ void split2(float v0, float v1, uint32_t& hi, uint32_t& lo) {
    __nv_bfloat16 h0 = __float2bfloat16_rn(v0);
    __nv_bfloat16 h1 = __float2bfloat16_rn(v1);
    __nv_bfloat16 l0 = __float2bfloat16_rn(v0 - __bfloat162float(h0));
    __nv_bfloat16 l1 = __float2bfloat16_rn(v1 - __bfloat162float(h1));
    hi = (uint32_t)__bfloat16_as_ushort(h0) | ((uint32_t)__bfloat16_as_ushort(h1) << 16);
    lo = (uint32_t)__bfloat16_as_ushort(l0) | ((uint32_t)__bfloat16_as_ushort(l1) << 16);
}
__device__ __forceinline__ void mma_bf16(float* c, const uint32_t* a, uint32_t b0, uint32_t b1) {
    asm volatile(
        "mma.sync.aligned.m16n8k16.row.col.f32.bf16.bf16.f32 "
        "{%0,%1,%2,%3}, {%4,%5,%6,%7}, {%8,%9}, {%0,%1,%2,%3};"
        : "+f"(c[0]), "+f"(c[1]), "+f"(c[2]), "+f"(c[3])
        : "r"(a[0]), "r"(a[1]), "r"(a[2]), "r"(a[3]), "r"(b0), "r"(b1));
}
__device__ __forceinline__ void ldm_x4(uint32_t* r, uint32_t addr) {
    asm volatile("ldmatrix.sync.aligned.m8n8.x4.shared.b16 {%0,%1,%2,%3}, [%4];"
        : "=r"(r[0]), "=r"(r[1]), "=r"(r[2]), "=r"(r[3]) : "r"(addr));
}
__device__ __forceinline__ void ldm_x4t(uint32_t* r, uint32_t addr) {
    asm volatile("ldmatrix.sync.aligned.m8n8.x4.trans.shared.b16 {%0,%1,%2,%3}, [%4];"
        : "=r"(r[0]), "=r"(r[1]), "=r"(r[2]), "=r"(r[3]) : "r"(addr));
}
__device__ __forceinline__ void cp16(uint32_t s, const void* g) {
    asm volatile("cp.async.cg.shared.global [%0], [%1], 16;" :: "r"(s), "l"(g));
}
#define CP_COMMIT() asm volatile("cp.async.commit_group;")
#define CP_WAIT(n)  asm volatile("cp.async.wait_group %0;" :: "n"(n))

// ===================== init + router =====================
__global__ void init_kernel(float* __restrict__ out) {
    int tid = blockIdx.x * blockDim.x + threadIdx.x;
    if (tid < NE) g_cnt[tid] = 0;
    int stride = gridDim.x * blockDim.x;
    for (int i = tid; i < NT * ND / 4; i += stride)
        *(float4*)&out[i * 4] = make_float4(0.f, 0.f, 0.f, 0.f);
}

__global__ void router_kernel(const float* __restrict__ x,
                              const float* __restrict__ gw) {
    int t    = (blockIdx.x * blockDim.x + threadIdx.x) >> 5;
    int lane = threadIdx.x & 31;
    if (t >= NT) return;
    const float* xr = x + (size_t)t * ND;
    float acc[NE];
#pragma unroll
    for (int e = 0; e < NE; e++) acc[e] = 0.f;
    for (int d = lane; d < ND; d += 32) {
        float xv = xr[d];
        const float* g = gw + d * NE;
#pragma unroll
        for (int e = 0; e < NE; e++) acc[e] = fmaf(xv, g[e], acc[e]);
    }
#pragma unroll
    for (int e = 0; e < NE; e++)
#pragma unroll
        for (int o = 16; o > 0; o >>= 1)
            acc[e] += __shfl_xor_sync(0xffffffffu, acc[e], o);
    if (lane == 0) {
        float m = acc[0];
#pragma unroll
        for (int e = 1; e < NE; e++) m = fmaxf(m, acc[e]);
        float Z = 0.f, p[NE];
#pragma unroll
        for (int e = 0; e < NE; e++) { p[e] = __expf(acc[e] - m); Z += p[e]; }
        int i1 = 0;
#pragma unroll
        for (int e = 1; e < NE; e++) if (p[e] > p[i1]) i1 = e;
        int i2 = (i1 == 0) ? 1 : 0;
#pragma unroll
        for (int e = 0; e < NE; e++) if (e != i1 && p[e] > p[i2]) i2 = e;
        float invZ = 1.f / Z;
        int pos = atomicAdd(&g_cnt[i1], 1);
        g_tok[i1 * NT + pos] = t; g_scl[i1 * NT + pos] = p[i1] * invZ;
        pos = atomicAdd(&g_cnt[i2], 1);
        g_tok[i2 * NT + pos] = t; g_scl[i2 * NT + pos] = p[i2] * invZ;
    }
}

// ===================== prep: split weights (layout preserved, k-major) =====================
__global__ void splitw_kernel(const float* __restrict__ src, int sel) {
    __nv_bfloat16* dh = (sel == 0) ? g_w1h : (sel == 1) ? g_w3h : g_w2h;
    __nv_bfloat16* dl = (sel == 0) ? g_w1l : (sel == 1) ? g_w3l : g_w2l;
    int i = blockIdx.x * blockDim.x + threadIdx.x;     // over n4 = NE*ND*NH/4
    float4 v = ((const float4*)src)[i];
    uint32_t h0, l0, h1, l1;
    split2(v.x, v.y, h0, l0);
    split2(v.z, v.w, h1, l1);
    ((uint2*)dh)[i] = make_uint2(h0, h1);
    ((uint2*)dl)[i] = make_uint2(l0, l1);
}

// ===================== prep: gather + scale + split routed A rows =====================
__global__ void prepa_kernel(const float* __restrict__ x) {
    int slot = blockIdx.x * 8 + (threadIdx.x >> 5);
    int e = slot >> 10, r = slot & (NT - 1);
    if (r >= g_cnt[e]) return;
    int lane = threadIdx.x & 31;
    int tok = g_tok[slot];
    float scl = g_scl[slot];
    const float* xr = x + (size_t)tok * ND;
    __nv_bfloat16* dh = g_ah + (size_t)slot * ND;
    __nv_bfloat16* dl = g_al + (size_t)slot * ND;
#pragma unroll
    for (int j = 0; j < 8; j++) {
        int idx = j * 128 + lane * 4;
        float4 v = *(const float4*)(xr + idx);
        uint32_t h0, l0, h1, l1;
        split2(v.x * scl, v.y * scl, h0, l0);
        split2(v.z * scl, v.w * scl, h1, l1);
        *(uint2*)(dh + idx) = make_uint2(h0, h1);
        *(uint2*)(dl + idx) = make_uint2(l0, l1);
    }
}

// ===================== smem layouts (uint32 units) =====================
#define ASTR   20          // A row stride (16 used)
#define S1_AL  1280
#define BSTR1  36          // gemm1 B k-row stride (32 used = 64 bf16)
#define S1_B   2560
#define S1_ARR 1152        // 32*36
#define S1_BUF 7168        // 2560 + 4*1152
#define BSTR2  68          // gemm2 B k-row stride (64 used = 128 bf16)
#define S2_B   2560
#define S2_ARR 2176        // 32*68
#define S2_BUF 6912        // 2560 + 2*2176

// ===================== gemm1: pure cp.async + ldmatrix + HMMA, fused SwiGLU ===
// CTA: 64 tokens x 64 hidden, dual (w1,w3). 8 warps 2(M)x4(N), warp 32x16 each.
__global__ __launch_bounds__(256, 2) void gemm1_tc() {
    const int e   = blockIdx.x >> 4;
    const int mt  = blockIdx.x & 15;
    const int cnt = g_cnt[e];
    const int m0  = mt * 64;
    if (m0 >= cnt) return;
    const int hb = blockIdx.y * 64;

    extern __shared__ uint32_t smu[];
    const uint32_t sb = (uint32_t)__cvta_generic_to_shared(smu);
    const int tid = threadIdx.x, wid = tid >> 5, lane = tid & 31;
    const int ty = lane >> 2, tx = lane & 3;
    const int warpM = (wid & 1) * 32, warpN = (wid >> 1) * 16;

    // ldmatrix lane addressing
    const int a_r = (lane & 7) + ((lane >> 3) & 1) * 8;
    const int a_c = ((lane >> 4) & 1) * 4;
    const uint32_t aAddr = sb + (uint32_t)(((warpM + a_r) * ASTR + a_c) * 4);
    const int b_k = (lane & 7) + ((lane >> 3) & 1) * 8;
    const int b_n = ((lane >> 4) & 1) * 8;
    const uint32_t bAddr = sb + (uint32_t)((S1_B + b_k * BSTR1 + (warpN + b_n) / 2) * 4);

    // cp.async producers: A (hi+lo), B (4 arrays)
    const int arow = tid >> 2, aj = tid & 3;
    const __nv_bfloat16* sAh = g_ah + (size_t)(e * NT + m0 + arow) * ND + aj * 8;
    const __nv_bfloat16* sAl = g_al + (size_t)(e * NT + m0 + arow) * ND + aj * 8;
    const uint32_t dA = (uint32_t)((arow * ASTR + aj * 4) * 4);

    const int arr = tid >> 6, rw = (tid & 63) >> 1, hf = tid & 1;
    const __nv_bfloat16* wsrc = (arr == 0) ? g_w1h : (arr == 1) ? g_w1l
                              : (arr == 2) ? g_w3h : g_w3l;
    const __nv_bfloat16* sB = wsrc + ((size_t)e * ND + rw) * NH + hb + hf * 32;
    const uint32_t dB = (uint32_t)((S1_B + arr * S1_ARR + rw * BSTR1 + hf * 16) * 4);

    float a1[2][2][4], a3[2][2][4];
#pragma unroll
    for (int m = 0; m < 2; m++)
#pragma unroll
        for (int n = 0; n < 2; n++)
#pragma unroll
            for (int r = 0; r < 4; r++) { a1[m][n][r] = 0.f; a3[m][n][r] = 0.f; }

    // prologue: chunk 0 -> buf0
    cp16(sb + dA, sAh);
    cp16(sb + dA + S1_AL * 4, sAl);
#pragma unroll
    for (int j = 0; j < 4; j++) cp16(sb + dB + j * 16, sB + j * 8);
    CP_COMMIT();

    const int NC = ND / 32;
    for (int kt = 0; kt < NC; kt++) {
        const int b = kt & 1;
        if (kt + 1 < NC) {
            const uint32_t bo = (uint32_t)(((kt + 1) & 1) * S1_BUF * 4);
            cp16(sb + bo + dA, sAh + (kt + 1) * 32);
            cp16(sb + bo + dA + S1_AL * 4, sAl + (kt + 1) * 32);
            const __nv_bfloat16* s = sB + (size_t)(kt + 1) * 32 * NH;
#pragma unroll
            for (int j = 0; j < 4; j++) cp16(sb + bo + dB + j * 16, s + j * 8);
            CP_COMMIT();
            CP_WAIT(1);
        } else {
            CP_WAIT(0);
        }
        __syncthreads();

        const uint32_t bo = (uint32_t)(b * S1_BUF * 4);
#pragma unroll
        for (int k16 = 0; k16 < 2; k16++) {
            uint32_t ah[2][4], al[2][4];
#pragma unroll
            for (int m = 0; m < 2; m++) {
                ldm_x4(ah[m], aAddr + bo + (uint32_t)((k16 * 8 + m * 16 * ASTR) * 4));
                ldm_x4(al[m], aAddr + bo + (uint32_t)((S1_AL + k16 * 8 + m * 16 * ASTR) * 4));
            }
            const uint32_t kB = bo + (uint32_t)(k16 * 16 * BSTR1 * 4);
            uint32_t b1h[4], b1l[4], b3h[4], b3l[4];
            ldm_x4t(b1h, bAddr + kB);
            ldm_x4t(b1l, bAddr + kB + S1_ARR * 4);
            ldm_x4t(b3h, bAddr + kB + 2 * S1_ARR * 4);
            ldm_x4t(b3l, bAddr + kB + 3 * S1_ARR * 4);
#pragma unroll
            for (int n = 0; n < 2; n++) {
#pragma unroll
                for (int m = 0; m < 2; m++) {
                    mma_bf16(a1[m][n], ah[m], b1h[2*n], b1h[2*n+1]);
                    mma_bf16(a1[m][n], al[m], b1h[2*n], b1h[2*n+1]);
                    mma_bf16(a1[m][n], ah[m], b1l[2*n], b1l[2*n+1]);
                    mma_bf16(a3[m][n], ah[m], b3h[2*n], b3h[2*n+1]);
                    mma_bf16(a3[m][n], al[m], b3h[2*n], b3h[2*n+1]);
                    mma_bf16(a3[m][n], ah[m], b3l[2*n], b3l[2*n+1]);
                }
            }
        }
        __syncthreads();
    }

    // epilogue: h = silu(a1)*a3, stored pre-split (bf16 hi/lo)
#pragma unroll
    for (int m = 0; m < 2; m++) {
        const int rr = m0 + warpM + m * 16 + ty;
#pragma unroll
        for (int n = 0; n < 2; n++) {
            const int col = hb + warpN + n * 8 + tx * 2;
            if (rr < cnt) {
                float g0 = a1[m][n][0], u0 = a3[m][n][0];
                float g1 = a1[m][n][1], u1 = a3[m][n][1];
                float s0 = (g0 / (1.f + __expf(-g0))) * u0;
                float s1 = (g1 / (1.f + __expf(-g1))) * u1;
                uint32_t hi, lo; split2(s0, s1, hi, lo);
                size_t idx = ((size_t)e * NT + rr) * NH + col;
                *(uint32_t*)&g_hh[idx] = hi;
                *(uint32_t*)&g_hl[idx] = lo;
            }
            if (rr + 8 < cnt) {
                float g0 = a1[m][n][2], u0 = a3[m][n][2];
                float g1 = a1[m][n][3], u1 = a3[m][n][3];
                float s0 = (g0 / (1.f + __expf(-g0))) * u0;
                float s1 = (g1 / (1.f + __expf(-g1))) * u1;
                uint32_t hi, lo; split2(s0, s1, hi, lo);
                size_t idx = ((size_t)e * NT + rr + 8) * NH + col;
                *(uint32_t*)&g_hh[idx] = hi;
                *(uint32_t*)&g_hl[idx] = lo;
            }
        }
    }
}

// ===================== gemm2: y = h @ w2, atomic scatter-combine =====================
// CTA: 64 x 128. 8 warps 2x4; warp 32x32.
__global__ __launch_bounds__(256, 2) void gemm2_tc(float* __restrict__ out) {
    const int e   = blockIdx.x >> 4;
    const int mt  = blockIdx.x & 15;
    const int cnt = g_cnt[e];
    const int m0  = mt * 64;
    if (m0 >= cnt) return;
    const int dbase = blockIdx.y * 128;

    extern __shared__ uint32_t smu[];
    const uint32_t sb = (uint32_t)__cvta_generic_to_shared(smu);
    const int tid = threadIdx.x, wid = tid >> 5, lane = tid & 31;
    const int ty = lane >> 2, tx = lane & 3;
    const int warpM = (wid & 1) * 32, warpN = (wid >> 1) * 32;

    const int a_r = (lane & 7) + ((lane >> 3) & 1) * 8;
    const int a_c = ((lane >> 4) & 1) * 4;
    const uint32_t aAddr = sb + (uint32_t)(((warpM + a_r) * ASTR + a_c) * 4);
    const int b_k = (lane & 7) + ((lane >> 3) & 1) * 8;
    const int b_n = ((lane >> 4) & 1) * 8;
    const uint32_t bAddr = sb + (uint32_t)((S2_B + b_k * BSTR2 + (warpN + b_n) / 2) * 4);

    const int arow = tid >> 2, aj = tid & 3;
    const __nv_bfloat16* sAh = g_hh + (size_t)(e * NT + m0 + arow) * NH + aj * 8;
    const __nv_bfloat16* sAl = g_hl + (size_t)(e * NT + m0 + arow) * NH + aj * 8;
    const uint32_t dA = (uint32_t)((arow * ASTR + aj * 4) * 4);

    const int arr = tid >> 7, rem = tid & 127, rw = rem >> 2, q = rem & 3;
    const __nv_bfloat16* wsrc = arr ? g_w2l : g_w2h;
    const __nv_bfloat16* sB = wsrc + ((size_t)e * NH + rw) * ND + dbase + q * 32;
    const uint32_t dB = (uint32_t)((S2_B + arr * S2_ARR + rw * BSTR2 + q * 16) * 4);

    float acc[2][4][4];
#pragma unroll
    for (int m = 0; m < 2; m++)
#pragma unroll
        for (int n = 0; n < 4; n++)
#pragma unroll
            for (int r = 0; r < 4; r++) acc[m][n][r] = 0.f;

    // prologue chunk 0 -> buf0
    cp16(sb + dA, sAh);
    cp16(sb + dA + S1_AL * 4, sAl);
#pragma unroll
    for (int j = 0; j < 4; j++) cp16(sb + dB + j * 16, sB + j * 8);
    CP_COMMIT();

    const int NC = NH / 32;
    for (int kt = 0; kt < NC; kt++) {
        const int b = kt & 1;
        if (kt + 1 < NC) {
            const uint32_t bo = (uint32_t)(((kt + 1) & 1) * S2_BUF * 4);
            cp16(sb + bo + dA, sAh + (kt + 1) * 32);
            cp16(sb + bo + dA + S1_AL * 4, sAl + (kt + 1) * 32);
            const __nv_bfloat16* s = sB + (size_t)(kt + 1) * 32 * ND;
#pragma unroll
            for (int j = 0; j < 4; j++) cp16(sb + bo + dB + j * 16, s + j * 8);
            CP_COMMIT();
            CP_WAIT(1);
        } else {
            CP_WAIT(0);
        }
        __syncthreads();

        const uint32_t bo = (uint32_t)(b * S2_BUF * 4);
#pragma unroll
        for (int k16 = 0; k16 < 2; k16++) {
            uint32_t ah[2][4], al[2][4];
#pragma unroll
            for (int m = 0; m < 2; m++) {
                ldm_x4(ah[m], aAddr + bo + (uint32_t)((k16 * 8 + m * 16 * ASTR) * 4));
                ldm_x4(al[m], aAddr + bo + (uint32_t)((S1_AL + k16 * 8 + m * 16 * ASTR) * 4));
            }
            const uint32_t kB = bo + (uint32_t)(k16 * 16 * BSTR2 * 4);
            uint32_t bh[2][4], bl[2][4];
#pragma unroll
            for (int g = 0; g < 2; g++) {
                ldm_x4t(bh[g], bAddr + kB + (uint32_t)(g * 8 * 4));
                ldm_x4t(bl[g], bAddr + kB + (uint32_t)((S2_ARR + g * 8) * 4));
            }
#pragma unroll
            for (int n = 0; n < 4; n++) {
                uint32_t h0 = bh[n >> 1][(n & 1) * 2], h1 = bh[n >> 1][(n & 1) * 2 + 1];
                uint32_t l0 = bl[n >> 1][(n & 1) * 2], l1 = bl[n >> 1][(n & 1) * 2 + 1];
#pragma unroll
                for (int m = 0; m < 2; m++) {
                    mma_bf16(acc[m][n], ah[m], h0, h1);
                    mma_bf16(acc[m][n], al[m], h0, h1);
                    mma_bf16(acc[m][n], ah[m], l0, l1);
                }
            }
        }
        __syncthreads();
    }

    // epilogue: atomic scatter-add (exactly 2 contributions/element)
#pragma unroll
    for (int m = 0; m < 2; m++) {
        const int r0 = m0 + warpM + m * 16 + ty;
        const int r1 = r0 + 8;
        const int tok0 = (r0 < cnt) ? g_tok[e * NT + r0] : -1;
        const int tok1 = (r1 < cnt) ? g_tok[e * NT + r1] : -1;
#pragma unroll
        for (int n = 0; n < 4; n++) {
            const int col = dbase + warpN + n * 8 + tx * 2;
            if (tok0 >= 0) {
                float* op = out + (size_t)tok0 * ND + col;
                atomicAdd(op,     acc[m][n][0]);
                atomicAdd(op + 1, acc[m][n][1]);
            }
            if (tok1 >= 0) {
                float* op = out + (size_t)tok1 * ND + col;
                atomicAdd(op,     acc[m][n][2]);
                atomicAdd(op + 1, acc[m][n][3]);
            }
        }
    }
}

// ===================== launch =====================
extern "C" void kernel_launch(void* const* d_in, const int* in_sizes, int n_in,
                              void* d_out, int out_size) {
    (void)in_sizes; (void)n_in; (void)out_size;
    const float* x  = (const float*)d_in[0];
    const float* gw = (const float*)d_in[1];
    const float* w1 = (const float*)d_in[2];
    const float* w2 = (const float*)d_in[3];
    const float* w3 = (const float*)d_in[4];
    float* out = (float*)d_out;

    const int SMEM1 = 2 * S1_BUF * 4;   // 57344 B
    const int SMEM2 = 2 * S2_BUF * 4;   // 55296 B
    cudaFuncSetAttribute(gemm1_tc, cudaFuncAttributeMaxDynamicSharedMemorySize, SMEM1);
    cudaFuncSetAttribute(gemm2_tc, cudaFuncAttributeMaxDynamicSharedMemorySize, SMEM2);

    const int n4 = NE * ND * NH / 4;    // 1048576
    init_kernel<<<256, 256>>>(out);
    splitw_kernel<<<n4 / 256, 256>>>(w1, 0);
    splitw_kernel<<<n4 / 256, 256>>>(w3, 1);
    splitw_kernel<<<n4 / 256, 256>>>(w2, 2);
    router_kernel<<<NT / 8, 256>>>(x, gw);
    prepa_kernel<<<NE * NT / 8, 256>>>(x);
    gemm1_tc<<<dim3(NE * 16, NH / 64), 256, SMEM1>>>();
    gemm2_tc<<<dim3(NE * 16, ND / 128), 256, SMEM2>>>(out);
}

// round 9
// speedup vs baseline: 1.2234x; 1.2234x over previous
#include <cuda_runtime.h>
#include <cuda_bf16.h>
#include <cstdint>

#define NT 1024   // tokens
#define ND 1024   // model dim
#define NH 512    // hidden dim
#define NE 8      // experts

// ---- static scratch ----
__device__ int   g_cnt[NE];
__device__ int   g_tok[NE * NT];
__device__ float g_scl[NE * NT];
__device__ __nv_bfloat16 g_ah[(size_t)NE * NT * ND];   // routed A, hi (bf16)
__device__ __nv_bfloat16 g_al[(size_t)NE * NT * ND];   // routed A, lo
__device__ __nv_bfloat16 g_hh[(size_t)NE * NT * NH];   // hidden hi
__device__ __nv_bfloat16 g_hl[(size_t)NE * NT * NH];   // hidden lo

// ===================== helpers =====================
__device__ __forceinline__ void split2(float v0, float v1, uint32_t& hi, uint32_t& lo) {
    __nv_bfloat16 h0 = __float2bfloat16_rn(v0);
    __nv_bfloat16 h1 = __float2bfloat16_rn(v1);
    __nv_bfloat16 l0 = __float2bfloat16_rn(v0 - __bfloat162float(h0));
    __nv_bfloat16 l1 = __float2bfloat16_rn(v1 - __bfloat162float(h1));
    hi = (uint32_t)__bfloat16_as_ushort(h0) | ((uint32_t)__bfloat16_as_ushort(h1) << 16);
    lo = (uint32_t)__bfloat16_as_ushort(l0) | ((uint32_t)__bfloat16_as_ushort(l1) << 16);
}
__device__ __forceinline__ void mma_bf16(float* c, const uint32_t* a, uint32_t b0, uint32_t b1) {
    asm volatile(
        "mma.sync.aligned.m16n8k16.row.col.f32.bf16.bf16.f32 "
        "{%0,%1,%2,%3}, {%4,%5,%6,%7}, {%8,%9}, {%0,%1,%2,%3};"
        : "+f"(c[0]), "+f"(c[1]), "+f"(c[2]), "+f"(c[3])
        : "r"(a[0]), "r"(a[1]), "r"(a[2]), "r"(a[3]), "r"(b0), "r"(b1));
}
// NOTE: "memory" clobber is load-bearing — producer STS follow in program
// order and must not be hoisted above these smem reads.
__device__ __forceinline__ void ldm_x4(uint32_t* r, uint32_t addr) {
    asm volatile("ldmatrix.sync.aligned.m8n8.x4.shared.b16 {%0,%1,%2,%3}, [%4];"
        : "=r"(r[0]), "=r"(r[1]), "=r"(r[2]), "=r"(r[3]) : "r"(addr) : "memory");
}
__device__ __forceinline__ void ldm_x4t(uint32_t* r, uint32_t addr) {
    asm volatile("ldmatrix.sync.aligned.m8n8.x4.trans.shared.b16 {%0,%1,%2,%3}, [%4];"
        : "=r"(r[0]), "=r"(r[1]), "=r"(r[2]), "=r"(r[3]) : "r"(addr) : "memory");
}

// ===================== init + router + prepa =====================
__global__ void init_kernel(float* __restrict__ out) {
    int tid = blockIdx.x * blockDim.x + threadIdx.x;
    if (tid < NE) g_cnt[tid] = 0;
    int stride = gridDim.x * blockDim.x;
    for (int i = tid; i < NT * ND / 4; i += stride)
        *(float4*)&out[i * 4] = make_float4(0.f, 0.f, 0.f, 0.f);
}

__global__ void router_kernel(const float* __restrict__ x,
                              const float* __restrict__ gw) {
    int t    = (blockIdx.x * blockDim.x + threadIdx.x) >> 5;
    int lane = threadIdx.x & 31;
    if (t >= NT) return;
    const float* xr = x + (size_t)t * ND;
    float acc[NE];
#pragma unroll
    for (int e = 0; e < NE; e++) acc[e] = 0.f;
    for (int d = lane; d < ND; d += 32) {
        float xv = xr[d];
        const float* g = gw + d * NE;
#pragma unroll
        for (int e = 0; e < NE; e++) acc[e] = fmaf(xv, g[e], acc[e]);
    }
#pragma unroll
    for (int e = 0; e < NE; e++)
#pragma unroll
        for (int o = 16; o > 0; o >>= 1)
            acc[e] += __shfl_xor_sync(0xffffffffu, acc[e], o);
    if (lane == 0) {
        float m = acc[0];
#pragma unroll
        for (int e = 1; e < NE; e++) m = fmaxf(m, acc[e]);
        float Z = 0.f, p[NE];
#pragma unroll
        for (int e = 0; e < NE; e++) { p[e] = __expf(acc[e] - m); Z += p[e]; }
        int i1 = 0;
#pragma unroll
        for (int e = 1; e < NE; e++) if (p[e] > p[i1]) i1 = e;
        int i2 = (i1 == 0) ? 1 : 0;
#pragma unroll
        for (int e = 0; e < NE; e++) if (e != i1 && p[e] > p[i2]) i2 = e;
        float invZ = 1.f / Z;
        int pos = atomicAdd(&g_cnt[i1], 1);
        g_tok[i1 * NT + pos] = t; g_scl[i1 * NT + pos] = p[i1] * invZ;
        pos = atomicAdd(&g_cnt[i2], 1);
        g_tok[i2 * NT + pos] = t; g_scl[i2 * NT + pos] = p[i2] * invZ;
    }
}

__global__ void prepa_kernel(const float* __restrict__ x) {
    int slot = blockIdx.x * 8 + (threadIdx.x >> 5);
    int e = slot >> 10, r = slot & (NT - 1);
    if (r >= g_cnt[e]) return;
    int lane = threadIdx.x & 31;
    int tok = g_tok[slot];
    float scl = g_scl[slot];
    const float* xr = x + (size_t)tok * ND;
    __nv_bfloat16* dh = g_ah + (size_t)slot * ND;
    __nv_bfloat16* dl = g_al + (size_t)slot * ND;
#pragma unroll
    for (int j = 0; j < 8; j++) {
        int idx = j * 128 + lane * 4;
        float4 v = *(const float4*)(xr + idx);
        uint32_t h0, l0, h1, l1;
        split2(v.x * scl, v.y * scl, h0, l0);
        split2(v.z * scl, v.w * scl, h1, l1);
        *(uint2*)(dh + idx) = make_uint2(h0, h1);
        *(uint2*)(dl + idx) = make_uint2(l0, l1);
    }
}

// ===================== smem layouts (uint32 units) =====================
#define ASTR   20          // A row stride (16 used)
#define S1_AL  1280
#define BSTR1  36          // gemm1 B k-row stride (32 used = 64 bf16)
#define S1_B   2560
#define S1_ARR 1152        // 32*36
#define S1_BUF 7168
#define BSTR2  68          // gemm2 B k-row stride (64 used = 128 bf16)
#define S2_B   2560
#define S2_ARR 2176        // 32*68
#define S2_BUF 6912

// ===================== gemm1: f32-weight split-on-fly, fused SwiGLU =========
// CTA: 64 tokens x 64 hidden, dual (w1,w3). 8 warps 2(M)x4(N), warp 32x16 each.
__global__ __launch_bounds__(256, 2) void gemm1_tc(
    const float* __restrict__ w1, const float* __restrict__ w3) {
    const int e   = blockIdx.x >> 4;
    const int mt  = blockIdx.x & 15;
    const int cnt = g_cnt[e];
    const int m0  = mt * 64;
    if (m0 >= cnt) return;
    const int hb = blockIdx.y * 64;

    extern __shared__ uint32_t smu[];
    const uint32_t sb = (uint32_t)__cvta_generic_to_shared(smu);
    const int tid = threadIdx.x, wid = tid >> 5, lane = tid & 31;
    const int ty = lane >> 2, tx = lane & 3;
    const int warpM = (wid & 1) * 32, warpN = (wid >> 1) * 16;

    // ldmatrix lane addressing (R8-validated)
    const int a_r = (lane & 7) + ((lane >> 3) & 1) * 8;
    const int a_c = ((lane >> 4) & 1) * 4;
    const uint32_t aAddr = sb + (uint32_t)(((warpM + a_r) * ASTR + a_c) * 4);
    const int b_k = (lane & 7) + ((lane >> 3) & 1) * 8;
    const int b_n = ((lane >> 4) & 1) * 8;
    const uint32_t bAddr = sb + (uint32_t)((S1_B + b_k * BSTR1 + (warpN + b_n) / 2) * 4);

    // A producer: 16B hi + 16B lo per thread per chunk
    const int arow = tid >> 2, aj = tid & 3;
    const __nv_bfloat16* sAh = g_ah + (size_t)(e * NT + m0 + arow) * ND + aj * 8;
    const __nv_bfloat16* sAl = g_al + (size_t)(e * NT + m0 + arow) * ND + aj * 8;
    const int dA = arow * ASTR + aj * 4;

    // B producer: sel matrix; 16 contiguous f32 per thread per chunk
    const int sel = tid >> 7, rem = tid & 127;
    const int krow = rem >> 2, seg = rem & 3;
    const float* wsel = (sel ? w3 : w1) + ((size_t)e * ND + krow) * NH + hb + seg * 16;
    const int dB = S1_B + sel * 2 * S1_ARR + krow * BSTR1 + seg * 8;  // hi; lo at +S1_ARR

    float a1[2][2][4], a3[2][2][4];
#pragma unroll
    for (int m = 0; m < 2; m++)
#pragma unroll
        for (int n = 0; n < 2; n++)
#pragma unroll
            for (int r = 0; r < 4; r++) { a1[m][n][r] = 0.f; a3[m][n][r] = 0.f; }

    uint4 pAh, pAl; float4 wr[4];

    // ---- prologue: chunk 0 -> buf 0 ----
    pAh = *(const uint4*)sAh; pAl = *(const uint4*)sAl;
#pragma unroll
    for (int j = 0; j < 4; j++) wr[j] = *(const float4*)(wsel + j * 4);
    {
        *(uint4*)&smu[dA] = pAh;
        *(uint4*)&smu[S1_AL + dA] = pAl;
        uint32_t h[8], l[8];
#pragma unroll
        for (int j = 0; j < 4; j++) {
            split2(wr[j].x, wr[j].y, h[2*j], l[2*j]);
            split2(wr[j].z, wr[j].w, h[2*j+1], l[2*j+1]);
        }
        *(uint4*)&smu[dB]     = make_uint4(h[0], h[1], h[2], h[3]);
        *(uint4*)&smu[dB + 4] = make_uint4(h[4], h[5], h[6], h[7]);
        *(uint4*)&smu[dB + S1_ARR]     = make_uint4(l[0], l[1], l[2], l[3]);
        *(uint4*)&smu[dB + S1_ARR + 4] = make_uint4(l[4], l[5], l[6], l[7]);
    }
    __syncthreads();

    const int NC = ND / 32;
    for (int kt = 0; kt < NC; kt++) {
        const int b = kt & 1;
        const bool nxt = (kt + 1) < NC;
        if (nxt) {
            pAh = *(const uint4*)(sAh + (kt + 1) * 32);
            pAl = *(const uint4*)(sAl + (kt + 1) * 32);
            const float* s = wsel + (size_t)(kt + 1) * 32 * NH;
#pragma unroll
            for (int j = 0; j < 4; j++) wr[j] = *(const float4*)(s + j * 4);
        }

        const uint32_t bo = (uint32_t)(b * S1_BUF * 4);
#pragma unroll
        for (int k16 = 0; k16 < 2; k16++) {
            uint32_t ah[2][4], al[2][4];
#pragma unroll
            for (int m = 0; m < 2; m++) {
                ldm_x4(ah[m], aAddr + bo + (uint32_t)((k16 * 8 + m * 16 * ASTR) * 4));
                ldm_x4(al[m], aAddr + bo + (uint32_t)((S1_AL + k16 * 8 + m * 16 * ASTR) * 4));
            }
            const uint32_t kB = bo + (uint32_t)(k16 * 16 * BSTR1 * 4);
            uint32_t b1h[4], b1l[4], b3h[4], b3l[4];
            ldm_x4t(b1h, bAddr + kB);
            ldm_x4t(b1l, bAddr + kB + S1_ARR * 4);
            ldm_x4t(b3h, bAddr + kB + 2 * S1_ARR * 4);
            ldm_x4t(b3l, bAddr + kB + 3 * S1_ARR * 4);
#pragma unroll
            for (int n = 0; n < 2; n++) {
#pragma unroll
                for (int m = 0; m < 2; m++) {
                    mma_bf16(a1[m][n], ah[m], b1h[2*n], b1h[2*n+1]);
                    mma_bf16(a1[m][n], al[m], b1h[2*n], b1h[2*n+1]);
                    mma_bf16(a1[m][n], ah[m], b1l[2*n], b1l[2*n+1]);
                    mma_bf16(a3[m][n], ah[m], b3h[2*n], b3h[2*n+1]);
                    mma_bf16(a3[m][n], al[m], b3h[2*n], b3h[2*n+1]);
                    mma_bf16(a3[m][n], ah[m], b3l[2*n], b3l[2*n+1]);
                }
            }
        }

        if (nxt) {   // producer stores AFTER all consumer reads of the other buf
            uint32_t* D = smu + ((kt + 1) & 1) * S1_BUF;
            *(uint4*)&D[dA] = pAh;
            *(uint4*)&D[S1_AL + dA] = pAl;
            uint32_t h[8], l[8];
#pragma unroll
            for (int j = 0; j < 4; j++) {
                split2(wr[j].x, wr[j].y, h[2*j], l[2*j]);
                split2(wr[j].z, wr[j].w, h[2*j+1], l[2*j+1]);
            }
            *(uint4*)&D[dB]     = make_uint4(h[0], h[1], h[2], h[3]);
            *(uint4*)&D[dB + 4] = make_uint4(h[4], h[5], h[6], h[7]);
            *(uint4*)&D[dB + S1_ARR]     = make_uint4(l[0], l[1], l[2], l[3]);
            *(uint4*)&D[dB + S1_ARR + 4] = make_uint4(l[4], l[5], l[6], l[7]);
        }
        __syncthreads();
    }

    // epilogue: h = silu(a1)*a3, stored pre-split (bf16 hi/lo)
#pragma unroll
    for (int m = 0; m < 2; m++) {
        const int rr = m0 + warpM + m * 16 + ty;
#pragma unroll
        for (int n = 0; n < 2; n++) {
            const int col = hb + warpN + n * 8 + tx * 2;
            if (rr < cnt) {
                float g0 = a1[m][n][0], u0 = a3[m][n][0];
                float g1 = a1[m][n][1], u1 = a3[m][n][1];
                float s0 = (g0 / (1.f + __expf(-g0))) * u0;
                float s1 = (g1 / (1.f + __expf(-g1))) * u1;
                uint32_t hi, lo; split2(s0, s1, hi, lo);
                size_t idx = ((size_t)e * NT + rr) * NH + col;
                *(uint32_t*)&g_hh[idx] = hi;
                *(uint32_t*)&g_hl[idx] = lo;
            }
            if (rr + 8 < cnt) {
                float g0 = a1[m][n][2], u0 = a3[m][n][2];
                float g1 = a1[m][n][3], u1 = a3[m][n][3];
                float s0 = (g0 / (1.f + __expf(-g0))) * u0;
                float s1 = (g1 / (1.f + __expf(-g1))) * u1;
                uint32_t hi, lo; split2(s0, s1, hi, lo);
                size_t idx = ((size_t)e * NT + rr + 8) * NH + col;
                *(uint32_t*)&g_hh[idx] = hi;
                *(uint32_t*)&g_hl[idx] = lo;
            }
        }
    }
}

// ===================== gemm2: y = h @ w2, atomic scatter-combine =============
// CTA: 64 x 128. 8 warps 2x4; warp 32x32.
__global__ __launch_bounds__(256, 2) void gemm2_tc(const float* __restrict__ w2,
                                                   float* __restrict__ out) {
    const int e   = blockIdx.x >> 4;
    const int mt  = blockIdx.x & 15;
    const int cnt = g_cnt[e];
    const int m0  = mt * 64;
    if (m0 >= cnt) return;
    const int dbase = blockIdx.y * 128;

    extern __shared__ uint32_t smu[];
    const uint32_t sb = (uint32_t)__cvta_generic_to_shared(smu);
    const int tid = threadIdx.x, wid = tid >> 5, lane = tid & 31;
    const int ty = lane >> 2, tx = lane & 3;
    const int warpM = (wid & 1) * 32, warpN = (wid >> 1) * 32;

    const int a_r = (lane & 7) + ((lane >> 3) & 1) * 8;
    const int a_c = ((lane >> 4) & 1) * 4;
    const uint32_t aAddr = sb + (uint32_t)(((warpM + a_r) * ASTR + a_c) * 4);
    const int b_k = (lane & 7) + ((lane >> 3) & 1) * 8;
    const int b_n = ((lane >> 4) & 1) * 8;
    const uint32_t bAddr = sb + (uint32_t)((S2_B + b_k * BSTR2 + (warpN + b_n) / 2) * 4);

    const int arow = tid >> 2, aj = tid & 3;
    const __nv_bfloat16* sAh = g_hh + (size_t)(e * NT + m0 + arow) * NH + aj * 8;
    const __nv_bfloat16* sAl = g_hl + (size_t)(e * NT + m0 + arow) * NH + aj * 8;
    const int dA = arow * ASTR + aj * 4;

    // B producer: 16 contiguous f32 per thread per chunk
    const int krow = tid >> 3, seg = tid & 7;
    const float* wb = w2 + ((size_t)e * NH + krow) * ND + dbase + seg * 16;
    const int dB = S2_B + krow * BSTR2 + seg * 8;     // hi; lo at +S2_ARR

    float acc[2][4][4];
#pragma unroll
    for (int m = 0; m < 2; m++)
#pragma unroll
        for (int n = 0; n < 4; n++)
#pragma unroll
            for (int r = 0; r < 4; r++) acc[m][n][r] = 0.f;

    uint4 pAh, pAl; float4 wr[4];

    // ---- prologue: chunk 0 -> buf 0 ----
    pAh = *(const uint4*)sAh; pAl = *(const uint4*)sAl;
#pragma unroll
    for (int j = 0; j < 4; j++) wr[j] = *(const float4*)(wb + j * 4);
    {
        *(uint4*)&smu[dA] = pAh;
        *(uint4*)&smu[S1_AL + dA] = pAl;
        uint32_t h[8], l[8];
#pragma unroll
        for (int j = 0; j < 4; j++) {
            split2(wr[j].x, wr[j].y, h[2*j], l[2*j]);
            split2(wr[j].z, wr[j].w, h[2*j+1], l[2*j+1]);
        }
        *(uint4*)&smu[dB]     = make_uint4(h[0], h[1], h[2], h[3]);
        *(uint4*)&smu[dB + 4] = make_uint4(h[4], h[5], h[6], h[7]);
        *(uint4*)&smu[dB + S2_ARR]     = make_uint4(l[0], l[1], l[2], l[3]);
        *(uint4*)&smu[dB + S2_ARR + 4] = make_uint4(l[4], l[5], l[6], l[7]);
    }
    __syncthreads();

    const int NC = NH / 32;
    for (int kt = 0; kt < NC; kt++) {
        const int b = kt & 1;
        const bool nxt = (kt + 1) < NC;
        if (nxt) {
            pAh = *(const uint4*)(sAh + (kt + 1) * 32);
            pAl = *(const uint4*)(sAl + (kt + 1) * 32);
            const float* s = wb + (size_t)(kt + 1) * 32 * ND;
#pragma unroll
            for (int j = 0; j < 4; j++) wr[j] = *(const float4*)(s + j * 4);
        }

        const uint32_t bo = (uint32_t)(b * S2_BUF * 4);
#pragma unroll
        for (int k16 = 0; k16 < 2; k16++) {
            uint32_t ah[2][4], al[2][4];
#pragma unroll
            for (int m = 0; m < 2; m++) {
                ldm_x4(ah[m], aAddr + bo + (uint32_t)((k16 * 8 + m * 16 * ASTR) * 4));
                ldm_x4(al[m], aAddr + bo + (uint32_t)((S1_AL + k16 * 8 + m * 16 * ASTR) * 4));
            }
            const uint32_t kB = bo + (uint32_t)(k16 * 16 * BSTR2 * 4);
            uint32_t bh[2][4], bl[2][4];
#pragma unroll
            for (int g = 0; g < 2; g++) {
                ldm_x4t(bh[g], bAddr + kB + (uint32_t)(g * 8 * 4));
                ldm_x4t(bl[g], bAddr + kB + (uint32_t)((S2_ARR + g * 8) * 4));
            }
#pragma unroll
            for (int n = 0; n < 4; n++) {
                uint32_t h0 = bh[n >> 1][(n & 1) * 2], h1 = bh[n >> 1][(n & 1) * 2 + 1];
                uint32_t l0 = bl[n >> 1][(n & 1) * 2], l1 = bl[n >> 1][(n & 1) * 2 + 1];
#pragma unroll
                for (int m = 0; m < 2; m++) {
                    mma_bf16(acc[m][n], ah[m], h0, h1);
                    mma_bf16(acc[m][n], al[m], h0, h1);
                    mma_bf16(acc[m][n], ah[m], l0, l1);
                }
            }
        }

        if (nxt) {
            uint32_t* D = smu + ((kt + 1) & 1) * S2_BUF;
            *(uint4*)&D[dA] = pAh;
            *(uint4*)&D[S1_AL + dA] = pAl;
            uint32_t h[8], l[8];
#pragma unroll
            for (int j = 0; j < 4; j++) {
                split2(wr[j].x, wr[j].y, h[2*j], l[2*j]);
                split2(wr[j].z, wr[j].w, h[2*j+1], l[2*j+1]);
            }
            *(uint4*)&D[dB]     = make_uint4(h[0], h[1], h[2], h[3]);
            *(uint4*)&D[dB + 4] = make_uint4(h[4], h[5], h[6], h[7]);
            *(uint4*)&D[dB + S2_ARR]     = make_uint4(l[0], l[1], l[2], l[3]);
            *(uint4*)&D[dB + S2_ARR + 4] = make_uint4(l[4], l[5], l[6], l[7]);
        }
        __syncthreads();
    }

    // epilogue: atomic scatter-add (exactly 2 contributions/element)
#pragma unroll
    for (int m = 0; m < 2; m++) {
        const int r0 = m0 + warpM + m * 16 + ty;
        const int r1 = r0 + 8;
        const int tok0 = (r0 < cnt) ? g_tok[e * NT + r0] : -1;
        const int tok1 = (r1 < cnt) ? g_tok[e * NT + r1] : -1;
#pragma unroll
        for (int n = 0; n < 4; n++) {
            const int col = dbase + warpN + n * 8 + tx * 2;
            if (tok0 >= 0) {
                float* op = out + (size_t)tok0 * ND + col;
                atomicAdd(op,     acc[m][n][0]);
                atomicAdd(op + 1, acc[m][n][1]);
            }
            if (tok1 >= 0) {
                float* op = out + (size_t)tok1 * ND + col;
                atomicAdd(op,     acc[m][n][2]);
                atomicAdd(op + 1, acc[m][n][3]);
            }
        }
    }
}

// ===================== launch =====================
extern "C" void kernel_launch(void* const* d_in, const int* in_sizes, int n_in,
                              void* d_out, int out_size) {
    (void)in_sizes; (void)n_in; (void)out_size;
    const float* x  = (const float*)d_in[0];
    const float* gw = (const float*)d_in[1];
    const float* w1 = (const float*)d_in[2];
    const float* w2 = (const float*)d_in[3];
    const float* w3 = (const float*)d_in[4];
    float* out = (float*)d_out;

    const int SMEM1 = 2 * S1_BUF * 4;   // 57344 B
    const int SMEM2 = 2 * S2_BUF * 4;   // 55296 B
    cudaFuncSetAttribute(gemm1_tc, cudaFuncAttributeMaxDynamicSharedMemorySize, SMEM1);
    cudaFuncSetAttribute(gemm2_tc, cudaFuncAttributeMaxDynamicSharedMemorySize, SMEM2);

    init_kernel<<<256, 256>>>(out);
    router_kernel<<<NT / 8, 256>>>(x, gw);
    prepa_kernel<<<NE * NT / 8, 256>>>(x);
    gemm1_tc<<<dim3(NE * 16, NH / 64), 256, SMEM1>>>(w1, w3);
    gemm2_tc<<<dim3(NE * 16, ND / 128), 256, SMEM2>>>(w2, out);
}